// round 1
// baseline (speedup 1.0000x reference)
#include <cuda_runtime.h>
#include <cuda_bf16.h>
#include <float.h>

// Segmented 3-NN cosine-consistency loss.
// Phase 1 (knn_loss_kernel): brute-force 3-NN per point within its segment
//   using smem-staged coords packed as (-2x,-2y,-2z,|c|^2); running top-3 with
//   e-space threshold so the hot loop is LDS.128 + 3 FFMA + compare.
//   Then gathers pred/target for the 3 neighbors, computes
//   (min(|cos(pn_i,pn_j)|,1) - min(|cos(t_i,t_j)|,1))^2 and block-reduces.
// Phase 2 (finalize_kernel): deterministic reduction of block partials.

#define THREADS 256
#define ROWS    256
#define SEG_MAX 4096   // smem tile capacity (points); segments larger are tiled

__device__ float g_partials[4096];

__device__ __forceinline__ float dot3(float ax, float ay, float az,
                                      float bx, float by, float bz) {
    return fmaf(ax, bx, fmaf(ay, by, az * bz));
}

__global__ void __launch_bounds__(THREADS)
knn_loss_kernel(const float* __restrict__ pred,
                const float* __restrict__ coord,
                const float* __restrict__ target,
                int seg, int nseg, int blocksPerSeg) {
    extern __shared__ float4 s_c[];   // SEG_MAX entries: (-2x,-2y,-2z,sq)

    const int segIdx  = blockIdx.x / blocksPerSeg;
    const int rowBase = (blockIdx.x % blocksPerSeg) * ROWS;
    const int i       = rowBase + threadIdx.x;          // local row in segment
    const bool active = (i < seg);
    const long segOff = (long)segIdx * seg;
    const long gi     = segOff + i;

    float xi = 0.f, yi = 0.f, zi = 0.f, sqi = 0.f;
    if (active) {
        xi  = coord[3 * gi + 0];
        yi  = coord[3 * gi + 1];
        zi  = coord[3 * gi + 2];
        sqi = xi * xi + yi * yi + zi * zi;
    }

    // running top-3 smallest clamped d2 (sorted D0 <= D1 <= D2)
    float D0 = FLT_MAX, D1 = FLT_MAX, D2 = FLT_MAX;
    int   I0 = -1, I1 = -1, I2 = -1;

    for (int jb = 0; jb < seg; jb += SEG_MAX) {
        const int tlen = min(SEG_MAX, seg - jb);

        __syncthreads();
        for (int t = threadIdx.x; t < tlen; t += blockDim.x) {
            const long gj = segOff + jb + t;
            float x = coord[3 * gj + 0];
            float y = coord[3 * gj + 1];
            float z = coord[3 * gj + 2];
            s_c[t] = make_float4(-2.f * x, -2.f * y, -2.f * z,
                                 x * x + y * y + z * z);
        }
        __syncthreads();

        if (active) {
            float thr = D2 - sqi;   // e-space threshold: e < thr <=> d2raw < D2
            #pragma unroll 4
            for (int t = 0; t < tlen; t++) {
                const float4 c = s_c[t];
                const float e = fmaf(c.x, xi, fmaf(c.y, yi, fmaf(c.z, zi, c.w)));
                if (e < thr) {
                    const int j = jb + t;
                    if (j != i) {
                        const float d = fmaxf(sqi + e, 0.0f);
                        if (d < D2) {   // strict <: ascending-j scan == lower-index tie-break
                            if (d < D0)      { D2=D1; I2=I1; D1=D0; I1=I0; D0=d; I0=j; }
                            else if (d < D1) { D2=D1; I2=I1; D1=d;  I1=j; }
                            else             { D2=d;  I2=j; }
                            thr = D2 - sqi;
                        }
                    }
                }
            }
        }
    }

    // ---- epilogue: neighbor similarity loss ----
    float acc = 0.0f;
    if (active) {
        // normalized pred for self
        float px = pred[3 * gi + 0], py = pred[3 * gi + 1], pz = pred[3 * gi + 2];
        float inpv = sqrtf(px * px + py * py + pz * pz + 1e-8f) + 1e-10f;
        float pnx = px / inpv, pny = py / inpv, pnz = pz / inpv;

        float tx = target[3 * gi + 0], ty = target[3 * gi + 1], tz = target[3 * gi + 2];

        const int nbr[3] = { I0, I1, I2 };
        #pragma unroll
        for (int k = 0; k < 3; k++) {
            const long gj = segOff + nbr[k];
            float qx = pred[3 * gj + 0], qy = pred[3 * gj + 1], qz = pred[3 * gj + 2];
            float inq = sqrtf(qx * qx + qy * qy + qz * qz + 1e-8f) + 1e-10f;
            float qnx = qx / inq, qny = qy / inq, qnz = qz / inq;

            float sim  = fminf(fabsf(dot3(qnx, qny, qnz, pnx, pny, pnz)), 1.0f);

            float ux = target[3 * gj + 0], uy = target[3 * gj + 1], uz = target[3 * gj + 2];
            float tsim = fminf(fabsf(dot3(ux, uy, uz, tx, ty, tz)), 1.0f);

            float diff = sim - tsim;
            acc = fmaf(diff, diff, acc);
        }
    }

    // ---- block reduction (deterministic) ----
    __shared__ float red[THREADS];
    red[threadIdx.x] = acc;
    __syncthreads();
    #pragma unroll
    for (int s = THREADS / 2; s > 0; s >>= 1) {
        if (threadIdx.x < s) red[threadIdx.x] += red[threadIdx.x + s];
        __syncthreads();
    }
    if (threadIdx.x == 0) g_partials[blockIdx.x] = red[0];
}

__global__ void __launch_bounds__(THREADS)
finalize_kernel(float* __restrict__ out, int nblocks, float invCount) {
    __shared__ float red[THREADS];
    float s = 0.0f;
    for (int b = threadIdx.x; b < nblocks; b += THREADS) s += g_partials[b];
    red[threadIdx.x] = s;
    __syncthreads();
    #pragma unroll
    for (int st = THREADS / 2; st > 0; st >>= 1) {
        if (threadIdx.x < st) red[threadIdx.x] += red[threadIdx.x + st];
        __syncthreads();
    }
    if (threadIdx.x == 0) out[0] = red[0] * invCount;
}

extern "C" void kernel_launch(void* const* d_in, const int* in_sizes, int n_in,
                              void* d_out, int out_size) {
    const float* pred   = (const float*)d_in[0];
    const float* coord  = (const float*)d_in[1];
    const float* target = (const float*)d_in[2];
    const int    nseg   = in_sizes[3];           // nums has nseg elements
    const int    npts   = in_sizes[0] / 3;
    const int    seg    = npts / nseg;

    const int blocksPerSeg = (seg + ROWS - 1) / ROWS;
    const int nblocks      = nseg * blocksPerSeg;
    const size_t smemBytes = (size_t)SEG_MAX * sizeof(float4);  // 64 KB

    static bool attrDone = false;
    if (!attrDone) {
        cudaFuncSetAttribute(knn_loss_kernel,
                             cudaFuncAttributeMaxDynamicSharedMemorySize,
                             (int)smemBytes);
        attrDone = true;
    }

    knn_loss_kernel<<<nblocks, THREADS, smemBytes>>>(pred, coord, target,
                                                     seg, nseg, blocksPerSeg);

    const float invCount = 1.0f / ((float)nseg * (float)seg * 3.0f);
    finalize_kernel<<<1, THREADS>>>((float*)d_out, nblocks, invCount);
}